// round 1
// baseline (speedup 1.0000x reference)
#include <cuda_runtime.h>

#define NROWS 2048
#define DIM   1024
#define KCENT 256
#define NGRP  512

// skewed index: spread binary-search address sets across smem banks
__device__ __forceinline__ int skew(int i) { return i + (i >> 5); }

// nearest centroid over sorted table (exact argmin semantics, tie -> lower idx)
__device__ __forceinline__ void quant1(float v, const float* __restrict__ sc,
                                       int& idx, float& q) {
    int pos = 0;
    #pragma unroll
    for (int s = 128; s >= 1; s >>= 1) {
        int np = pos + s;                 // always <= 255
        float cv = sc[skew(np)];
        if (cv <= v) pos = np;
    }
    float c0 = sc[skew(pos)];
    int   p1 = pos + 1; if (p1 > KCENT - 1) p1 = KCENT - 1;
    float c1 = sc[skew(p1)];
    float d0 = fabsf(v - c0);
    float d1 = fabsf(v - c1);
    if (d1 < d0) { idx = p1;  q = c1; }
    else         { idx = pos; q = c0; }   // tie -> lower index (matches argmin)
}

__global__ __launch_bounds__(256)
void planar_quant_kernel(const float* __restrict__ x,
                         const float* __restrict__ centroids,
                         const float* __restrict__ rot2,
                         float* __restrict__ out_xhat,
                         float* __restrict__ out_idx,
                         int write_idx) {
    __shared__ float sc[KCENT + (KCENT >> 5)];   // skewed centroid table
    __shared__ float sred[8];

    const int row = blockIdx.x;
    const int t   = threadIdx.x;

    // cooperative centroid load into skewed smem
    if (t < KCENT) sc[skew(t)] = centroids[t];

    // one float4 per thread covers elements [4t, 4t+3] = groups 2t, 2t+1
    const float4 xv = reinterpret_cast<const float4*>(x + (size_t)row * DIM)[t];

    // block sum of squares
    float ss = xv.x * xv.x + xv.y * xv.y + xv.z * xv.z + xv.w * xv.w;
    #pragma unroll
    for (int o = 16; o; o >>= 1) ss += __shfl_xor_sync(0xffffffffu, ss, o);
    if ((t & 31) == 0) sred[t >> 5] = ss;
    __syncthreads();

    float total = 0.f;
    #pragma unroll
    for (int i = 0; i < 8; i++) total += sred[i];

    float norm = sqrtf(total);
    norm = fmaxf(norm, 1e-8f);
    const float rn = 1.0f / norm;

    // rotation params for groups 2t (rv.x,rv.y) and 2t+1 (rv.z,rv.w)
    const float4 rv = reinterpret_cast<const float4*>(rot2)[t];

    const float v0 = xv.x * rn, v1 = xv.y * rn;
    const float v2 = xv.z * rn, v3 = xv.w * rn;

    const float r0 = rv.x * v0 - rv.y * v1;
    const float r1 = rv.y * v0 + rv.x * v1;
    const float r2 = rv.z * v2 - rv.w * v3;
    const float r3 = rv.w * v2 + rv.z * v3;

    int   i0, i1, i2, i3;
    float q0, q1, q2, q3;
    quant1(r0, sc, i0, q0);
    quant1(r1, sc, i1, q1);
    quant1(r2, sc, i2, q2);
    quant1(r3, sc, i3, q3);

    // inverse rotation, rescale
    float4 xh;
    xh.x = ( rv.x * q0 + rv.y * q1) * norm;
    xh.y = (-rv.y * q0 + rv.x * q1) * norm;
    xh.z = ( rv.z * q2 + rv.w * q3) * norm;
    xh.w = (-rv.w * q2 + rv.z * q3) * norm;
    reinterpret_cast<float4*>(out_xhat + (size_t)row * DIM)[t] = xh;

    if (write_idx) {
        float4 fi;
        fi.x = (float)i0; fi.y = (float)i1; fi.z = (float)i2; fi.w = (float)i3;
        reinterpret_cast<float4*>(out_idx + (size_t)row * DIM)[t] = fi;
    }
}

extern "C" void kernel_launch(void* const* d_in, const int* in_sizes, int n_in,
                              void* d_out, int out_size) {
    const float* x         = (const float*)d_in[0];  // [2048, 1024]
    const float* centroids = (const float*)d_in[1];  // [256]
    const float* rot2      = (const float*)d_in[2];  // [512, 2]

    float* out = (float*)d_out;
    const int full = (out_size >= 2 * NROWS * DIM);
    float* out_xhat = out;
    float* out_idx  = full ? out + (size_t)NROWS * DIM : out;

    planar_quant_kernel<<<NROWS, 256>>>(x, centroids, rot2,
                                        out_xhat, out_idx, full);
}